// round 6
// baseline (speedup 1.0000x reference)
#include <cuda_runtime.h>
#include <cstdint>

#define F        128
#define TM       128
#define NTHREADS 256
#define NRBF     20

// smem offsets in FLOATS
#define OFF_S    0            // s tile  [128][136] k-pair interleaved   17408
#define OFF_B    17408        // W_phi chunk [128n][136] interleaved     17408
#define OFF_RBF  34816        // rbf [128][28] direct                     3584
#define OFF_WW   38400        // W_w [3][128n][28k] direct               10752
#define OFF_IDX  49152        // 128 ints
#define OFF_RN   49280        // 128 * 4 floats
#define OFF_G    49792        // 1 float: rsqrt(frobenius^2)
#define SMEM_FLOATS 49824
#define SMEM_BYTES  (SMEM_FLOATS * 4)

__device__ float g_part[512];

static __device__ __forceinline__ uint32_t to_tf32(float x){
  uint32_t t;
  asm("cvt.rna.tf32.f32 %0, %1;" : "=r"(t) : "f"(x));
  return t;
}
static __device__ __forceinline__ void mma8(float c[4], uint32_t a0, uint32_t a1,
    uint32_t a2, uint32_t a3, uint32_t b0, uint32_t b1){
  asm volatile("mma.sync.aligned.m16n8k8.row.col.f32.tf32.tf32.f32 "
    "{%0,%1,%2,%3}, {%4,%5,%6,%7}, {%8,%9}, {%0,%1,%2,%3};"
    : "+f"(c[0]), "+f"(c[1]), "+f"(c[2]), "+f"(c[3])
    : "r"(a0), "r"(a1), "r"(a2), "r"(a3), "r"(b0), "r"(b1));
}
static __device__ __forceinline__ void red4(float* p, float a, float b, float c, float d){
  asm volatile("red.global.add.v4.f32 [%0], {%1, %2, %3, %4};"
               :: "l"(p), "f"(a), "f"(b), "f"(c), "f"(d) : "memory");
}
// interleaved pair position for k in 0..127 (or 0..23 for Ww-style widths)
static __device__ __forceinline__ int pairpos(int k){
  return (k >> 3) * 8 + (k & 3) * 2 + ((k >> 2) & 1);
}

__global__ void reduce_zero_kernel(const float* __restrict__ r, int n,
                                   float4* __restrict__ out4, int nout4){
  for (int i = blockIdx.x * blockDim.x + threadIdx.x; i < nout4; i += gridDim.x * blockDim.x)
    out4[i] = make_float4(0.f, 0.f, 0.f, 0.f);
  float s = 0.f;
  for (int i = blockIdx.x * blockDim.x + threadIdx.x; i < n; i += gridDim.x * blockDim.x){
    float x = r[i];
    s = fmaf(x, x, s);
  }
  #pragma unroll
  for (int o = 16; o > 0; o >>= 1) s += __shfl_xor_sync(0xffffffffu, s, o);
  __shared__ float ws[8];
  int lane = threadIdx.x & 31, w = threadIdx.x >> 5;
  if (lane == 0) ws[w] = s;
  __syncthreads();
  if (threadIdx.x < 32){
    s = (threadIdx.x < 8) ? ws[threadIdx.x] : 0.f;
    #pragma unroll
    for (int o = 4; o > 0; o >>= 1) s += __shfl_xor_sync(0xffffffffu, s, o);
    if (threadIdx.x == 0) g_part[blockIdx.x] = s;
  }
}

// MODE 0: store gated c=0 (sv) in regs; MODE 1: scatter out_s; MODE 2: combine -> out_v
template<int MODE>
static __device__ __forceinline__ void run_chunk(
    const uint32_t* __restrict__ su, const float* __restrict__ smf,
    int wid, int lane, int eb, int E, int c,
    const float* __restrict__ bphi_g, const float* __restrict__ bw_g,
    const float* __restrict__ v_g,
    float* __restrict__ out_s, float* __restrict__ out_v,
    float (*sv)[4])
{
  const int g    = wid >> 1;          // edge group (32 edges)
  const int half = wid & 1;           // n half (64 cols)
  const int qr   = lane >> 2;
  const int kb   = lane & 3;
  const int rA0  = g * 32 + qr;       // mt=0 row base ; mt=1 adds 16
  const int nb   = half * 64;

  float acc[2][8][4];
  #pragma unroll
  for (int mt = 0; mt < 2; mt++)
    #pragma unroll
    for (int nt = 0; nt < 8; nt++){
      acc[mt][nt][0]=0.f; acc[mt][nt][1]=0.f; acc[mt][nt][2]=0.f; acc[mt][nt][3]=0.f;
    }

  // ---- phi = s @ Wphi_chunk : balanced 32x64 tile, LDS.64 pair loads ----
  #pragma unroll 4
  for (int ks = 0; ks < 16; ks++){
    const int kp = ks * 8 + kb * 2;
    uint2 a00 = *(const uint2*)(su + OFF_S + (rA0     )*136 + kp);
    uint2 a01 = *(const uint2*)(su + OFF_S + (rA0 +  8)*136 + kp);
    uint2 a10 = *(const uint2*)(su + OFF_S + (rA0 + 16)*136 + kp);
    uint2 a11 = *(const uint2*)(su + OFF_S + (rA0 + 24)*136 + kp);
    #pragma unroll
    for (int nt = 0; nt < 8; nt++){
      const int n = nb + nt * 8 + qr;
      uint2 b = *(const uint2*)(su + OFF_B + n*136 + kp);
      mma8(acc[0][nt], a00.x, a01.x, a00.y, a01.y, b.x, b.y);
      mma8(acc[1][nt], a10.x, a11.x, a10.y, a11.y, b.x, b.y);
    }
  }

  // ---- rbf fragments (K padded 20->24) for both m-tiles ----
  uint32_t ra[2][3][4];
  #pragma unroll
  for (int mt = 0; mt < 2; mt++){
    const int rm = rA0 + mt * 16;
    #pragma unroll
    for (int ks = 0; ks < 3; ks++){
      const int k = ks * 8 + kb;
      ra[mt][ks][0] = su[OFF_RBF + rm*28 + k];
      ra[mt][ks][1] = su[OFF_RBF + (rm+8)*28 + k];
      ra[mt][ks][2] = su[OFF_RBF + rm*28 + k + 4];
      ra[mt][ks][3] = su[OFF_RBF + (rm+8)*28 + k + 4];
    }
  }

  const bool even = (kb & 1) == 0;
  int   nodeT[2], eT[2];
  float rx[2], ry[2], rz[2];
  #pragma unroll
  for (int mt = 0; mt < 2; mt++){
    const int rowT = g*32 + mt*16 + qr + (even ? 0 : 8);
    eT[mt]    = eb + rowT;
    nodeT[mt] = ((const int*)(smf + OFF_IDX))[rowT];
    if (MODE == 2){
      rx[mt] = smf[OFF_RN + rowT*4 + 0];
      ry[mt] = smf[OFF_RN + rowT*4 + 1];
      rz[mt] = smf[OFF_RN + rowT*4 + 2];
    }
  }
  const int cb0 = (kb >> 1) * 4;      // merged col base within n-tile

  #pragma unroll
  for (int nt = 0; nt < 8; nt++){
    const int n = nb + nt * 8 + qr;
    const int cc = nb + nt * 8 + 2 * kb;
    const float2 bp = *(const float2*)(bphi_g + c*F + cc);
    const float2 bw = *(const float2*)(bw_g   + c*F + cc);
    #pragma unroll
    for (int mt = 0; mt < 2; mt++){
      // w = rbf @ Ww_chunk
      float w4[4] = {0.f, 0.f, 0.f, 0.f};
      #pragma unroll
      for (int ks = 0; ks < 3; ks++){
        const int k = ks * 8 + kb;
        uint32_t wb0 = su[OFF_WW + (c*128 + n)*28 + k];
        uint32_t wb1 = su[OFF_WW + (c*128 + n)*28 + k + 4];
        mma8(w4, ra[mt][ks][0], ra[mt][ks][1], ra[mt][ks][2], ra[mt][ks][3], wb0, wb1);
      }
      float s0 = (w4[0] + bw.x) * (acc[mt][nt][0] + bp.x);
      float s1 = (w4[1] + bw.y) * (acc[mt][nt][1] + bp.y);
      float s2 = (w4[2] + bw.x) * (acc[mt][nt][2] + bp.x);
      float s3 = (w4[3] + bw.y) * (acc[mt][nt][3] + bp.y);

      if (MODE == 0){
        sv[mt*8 + nt][0] = s0; sv[mt*8 + nt][1] = s1;
        sv[mt*8 + nt][2] = s2; sv[mt*8 + nt][3] = s3;
      } else if (MODE == 1){
        float x0 = __shfl_xor_sync(0xffffffffu, s0, 1);
        float x1 = __shfl_xor_sync(0xffffffffu, s1, 1);
        float x2 = __shfl_xor_sync(0xffffffffu, s2, 1);
        float x3 = __shfl_xor_sync(0xffffffffu, s3, 1);
        float q0 = even ? s0 : x2, q1 = even ? s1 : x3;
        float q2 = even ? x0 : s2, q3 = even ? x1 : s3;
        if (eT[mt] < E)
          red4(out_s + (size_t)nodeT[mt]*F + nb + nt*8 + cb0, q0, q1, q2, q3);
      } else {
        float* svp = sv[mt*8 + nt];
        float y0 = __shfl_xor_sync(0xffffffffu, svp[0], 1);
        float y1 = __shfl_xor_sync(0xffffffffu, svp[1], 1);
        float y2 = __shfl_xor_sync(0xffffffffu, svp[2], 1);
        float y3 = __shfl_xor_sync(0xffffffffu, svp[3], 1);
        float x0 = __shfl_xor_sync(0xffffffffu, s0, 1);
        float x1 = __shfl_xor_sync(0xffffffffu, s1, 1);
        float x2 = __shfl_xor_sync(0xffffffffu, s2, 1);
        float x3 = __shfl_xor_sync(0xffffffffu, s3, 1);
        float pv0 = even ? svp[0] : y2, pv1 = even ? svp[1] : y3;
        float pv2 = even ? y0 : svp[2], pv3 = even ? y1 : svp[3];
        float pr0 = even ? s0 : x2, pr1 = even ? s1 : x3;
        float pr2 = even ? x0 : s2, pr3 = even ? x1 : s3;
        if (eT[mt] < E){
          const float* vp = v_g   + (size_t)eT[mt]   * 3*F + nb + nt*8 + cb0;
          float*       op = out_v + (size_t)nodeT[mt] * 3*F + nb + nt*8 + cb0;
          #pragma unroll
          for (int d = 0; d < 3; d++){
            const float rd = (d == 0) ? rx[mt] : (d == 1) ? ry[mt] : rz[mt];
            const float4 vv = *(const float4*)(vp + d*F);
            red4(op + d*F,
                 fmaf(pv0, vv.x, pr0*rd), fmaf(pv1, vv.y, pr1*rd),
                 fmaf(pv2, vv.z, pr2*rd), fmaf(pv3, vv.w, pr3*rd));
          }
        }
      }
    }
  }
}

static __device__ __forceinline__ void stage_B(uint32_t* __restrict__ su,
    const float* __restrict__ Wp_g, int c, int tid){
  #pragma unroll 8
  for (int it = 0; it < 64; it++){
    int i = it * NTHREADS + tid;       // 16384 elements, coalesced over n
    int kk = i >> 7, n = i & 127;
    su[OFF_B + n*136 + pairpos(kk)] = to_tf32(Wp_g[kk*384 + c*128 + n]);
  }
}

__global__ void __launch_bounds__(NTHREADS)
fused_message_kernel(
    const float* __restrict__ s_g, const float* __restrict__ r_g,
    const float* __restrict__ v_g, const int*   __restrict__ idx_g,
    const float* __restrict__ Wp_g, const float* __restrict__ bphi_g,
    const float* __restrict__ Ww_g, const float* __restrict__ bw_g,
    float* __restrict__ out_v, float* __restrict__ out_s, int E)
{
  extern __shared__ float smf[];
  uint32_t* su = (uint32_t*)smf;
  const int tid  = threadIdx.x;
  const int wid  = tid >> 5;
  const int lane = tid & 31;
  const int eb   = blockIdx.x * TM;

  // ---- prologue ----
  // warp 0: deterministic sum of frobenius partials
  if (wid == 0){
    float gs = 0.f;
    #pragma unroll
    for (int j = 0; j < 16; j++) gs += g_part[lane + 32*j];
    #pragma unroll
    for (int o = 16; o > 0; o >>= 1) gs += __shfl_xor_sync(0xffffffffu, gs, o);
    if (lane == 0) smf[OFF_G] = rsqrtf(gs);
  }
  // s tile -> tf32 [128][136] interleaved
  {
    const float4* s4 = (const float4*)s_g;
    #pragma unroll
    for (int it = 0; it < 16; it++){
      int i = it * NTHREADS + tid;      // 4096 float4
      int m = i >> 5, q = i & 31;
      float4 val = make_float4(0.f, 0.f, 0.f, 0.f);
      if (eb + m < E) val = s4[(size_t)(eb + m) * 32 + q];
      int base = m*136 + (q >> 1)*8 + (q & 1);   // pairpos(4q + j) = base + 2j
      su[OFF_S + base + 0] = to_tf32(val.x);
      su[OFF_S + base + 2] = to_tf32(val.y);
      su[OFF_S + base + 4] = to_tf32(val.z);
      su[OFF_S + base + 6] = to_tf32(val.w);
    }
  }
  // zero k=20..23 pads of rbf and Ww (direct layouts)
  if (tid < 128) *(float4*)(smf + OFF_RBF + tid*28 + 20) = make_float4(0.f,0.f,0.f,0.f);
  for (int i = tid; i < 384; i += NTHREADS)
    *(float4*)(smf + OFF_WW + i*28 + 20) = make_float4(0.f,0.f,0.f,0.f);
  // Ww -> [3][128n][28k]
  for (int i = tid; i < NRBF * 384; i += NTHREADS){
    int kk = i / 384, gg = i % 384;
    int c = gg >> 7, n = gg & 127;
    su[OFF_WW + (c*128 + n)*28 + kk] = to_tf32(Ww_g[i]);
  }
  __syncthreads();   // g ready
  // rbf / rn / idx
  if (tid < TM){
    int ee = eb + tid;
    float rxv = 0.f, ryv = 0.f, rzv = 0.f;
    int node = 0;
    if (ee < E){
      rxv = r_g[3*ee+0]; ryv = r_g[3*ee+1]; rzv = r_g[3*ee+2];
      node = idx_g[ee];
    }
    ((int*)(smf + OFF_IDX))[tid] = node;
    float rn = sqrtf(fmaf(rxv,rxv, fmaf(ryv,ryv, rzv*rzv)));
    float invg = smf[OFF_G];
    smf[OFF_RN + tid*4+0] = rxv*invg;
    smf[OFF_RN + tid*4+1] = ryv*invg;
    smf[OFF_RN + tid*4+2] = rzv*invg;
    smf[OFF_RN + tid*4+3] = 0.f;
    if (ee < E){
      float inv_rn = 1.f / rn;
      const float c0 = 0.62831853071795864769f;  // pi / R_CUT
      #pragma unroll
      for (int k = 0; k < NRBF; k++){
        float t  = sinf((float)(k+1) * c0 * rn) * inv_rn;
        float rb = (t <= 5.0f) ? 0.5f*(cosf(c0*t) + 1.f) : 0.f;
        su[OFF_RBF + tid*28 + k] = to_tf32(rb);
      }
    } else {
      #pragma unroll
      for (int k = 0; k < NRBF; k++) su[OFF_RBF + tid*28 + k] = 0u;
    }
  }

  float sv[16][4];

  // chunk c=1 -> out_s
  stage_B(su, Wp_g, 1, tid);
  __syncthreads();
  run_chunk<1>(su, smf, wid, lane, eb, E, 1, bphi_g, bw_g, v_g, out_s, out_v, sv);
  __syncthreads();
  // chunk c=0 -> sv (registers)
  stage_B(su, Wp_g, 0, tid);
  __syncthreads();
  run_chunk<0>(su, smf, wid, lane, eb, E, 0, bphi_g, bw_g, v_g, out_s, out_v, sv);
  __syncthreads();
  // chunk c=2 -> sr, combine with sv and v -> out_v
  stage_B(su, Wp_g, 2, tid);
  __syncthreads();
  run_chunk<2>(su, smf, wid, lane, eb, E, 2, bphi_g, bw_g, v_g, out_s, out_v, sv);
}

extern "C" void kernel_launch(void* const* d_in, const int* in_sizes, int n_in,
                              void* d_out, int out_size){
  const float* s_g  = (const float*)d_in[0];
  const float* r_g  = (const float*)d_in[1];
  const float* v_g  = (const float*)d_in[2];
  const int*   idx  = (const int*)  d_in[3];
  const float* Wp   = (const float*)d_in[4];
  const float* bphi = (const float*)d_in[5];
  const float* Ww   = (const float*)d_in[6];
  const float* bw   = (const float*)d_in[7];
  const int E = in_sizes[1] / 3;            // r is (E,3)
  const int N = out_size / (4*F);           // out = out_v (N*3*F) ++ out_s (N*F)
  float* out_v = (float*)d_out;
  float* out_s = out_v + (size_t)N*3*F;

  reduce_zero_kernel<<<512, 256>>>(r_g, 3*E, (float4*)d_out, out_size/4);
  cudaFuncSetAttribute(fused_message_kernel,
                       cudaFuncAttributeMaxDynamicSharedMemorySize, SMEM_BYTES);
  const int blocks = (E + TM - 1) / TM;
  fused_message_kernel<<<blocks, NTHREADS, SMEM_BYTES>>>(
      s_g, r_g, v_g, idx, Wp, bphi, Ww, bw, out_v, out_s, E);
}

// round 7
// speedup vs baseline: 1.0814x; 1.0814x over previous
#include <cuda_runtime.h>
#include <cstdint>

#define F        128
#define TM       128
#define NTHREADS 512
#define NRBF     20

// smem offsets in FLOATS
#define OFF_S    0            // s tile  [128][136] k-pair interleaved   17408
#define OFF_B    17408        // W_phi chunk [128n][136] interleaved     17408
#define OFF_RBF  34816        // rbf [128][28] direct                     3584
#define OFF_WW   38400        // W_w [3][128n][28k] direct               10752
#define OFF_IDX  49152        // 128 ints
#define OFF_RN   49280        // 128 * 4 floats
#define OFF_G    49792        // 1 float: rsqrt(frobenius^2)
#define SMEM_FLOATS 49824
#define SMEM_BYTES  (SMEM_FLOATS * 4)

__device__ float g_part[512];

static __device__ __forceinline__ uint32_t to_tf32(float x){
  uint32_t t;
  asm("cvt.rna.tf32.f32 %0, %1;" : "=r"(t) : "f"(x));
  return t;
}
static __device__ __forceinline__ void mma8(float c[4], uint32_t a0, uint32_t a1,
    uint32_t a2, uint32_t a3, uint32_t b0, uint32_t b1){
  asm volatile("mma.sync.aligned.m16n8k8.row.col.f32.tf32.tf32.f32 "
    "{%0,%1,%2,%3}, {%4,%5,%6,%7}, {%8,%9}, {%0,%1,%2,%3};"
    : "+f"(c[0]), "+f"(c[1]), "+f"(c[2]), "+f"(c[3])
    : "r"(a0), "r"(a1), "r"(a2), "r"(a3), "r"(b0), "r"(b1));
}
static __device__ __forceinline__ void red4(float* p, float a, float b, float c, float d){
  asm volatile("red.global.add.v4.f32 [%0], {%1, %2, %3, %4};"
               :: "l"(p), "f"(a), "f"(b), "f"(c), "f"(d) : "memory");
}
// interleaved pair position for k in 0..127
static __device__ __forceinline__ int pairpos(int k){
  return (k >> 3) * 8 + (k & 3) * 2 + ((k >> 2) & 1);
}

__global__ void reduce_zero_kernel(const float* __restrict__ r, int n,
                                   float4* __restrict__ out4, int nout4){
  for (int i = blockIdx.x * blockDim.x + threadIdx.x; i < nout4; i += gridDim.x * blockDim.x)
    out4[i] = make_float4(0.f, 0.f, 0.f, 0.f);
  float s = 0.f;
  for (int i = blockIdx.x * blockDim.x + threadIdx.x; i < n; i += gridDim.x * blockDim.x){
    float x = r[i];
    s = fmaf(x, x, s);
  }
  #pragma unroll
  for (int o = 16; o > 0; o >>= 1) s += __shfl_xor_sync(0xffffffffu, s, o);
  __shared__ float ws[8];
  int lane = threadIdx.x & 31, w = threadIdx.x >> 5;
  if (lane == 0) ws[w] = s;
  __syncthreads();
  if (threadIdx.x < 32){
    s = (threadIdx.x < 8) ? ws[threadIdx.x] : 0.f;
    #pragma unroll
    for (int o = 4; o > 0; o >>= 1) s += __shfl_xor_sync(0xffffffffu, s, o);
    if (threadIdx.x == 0) g_part[blockIdx.x] = s;
  }
}

// MODE 0: store gated c=0 (sv) in regs; MODE 1: scatter out_s; MODE 2: combine -> out_v
template<int MODE>
static __device__ __forceinline__ void run_chunk(
    const uint32_t* __restrict__ su, const float* __restrict__ smf,
    int wid, int lane, int eb, int E, int c,
    const float* __restrict__ bphi_g, const float* __restrict__ bw_g,
    const float* __restrict__ v_g,
    float* __restrict__ out_s, float* __restrict__ out_v,
    float (*sv)[4])
{
  const int mg   = wid >> 1;          // m-group: 16 edges
  const int half = wid & 1;           // n half (64 cols)
  const int qr   = lane >> 2;
  const int kb   = lane & 3;
  const int rA0  = mg * 16 + qr;
  const int nb   = half * 64;

  float acc[8][4];
  #pragma unroll
  for (int nt = 0; nt < 8; nt++){
    acc[nt][0]=0.f; acc[nt][1]=0.f; acc[nt][2]=0.f; acc[nt][3]=0.f;
  }

  // ---- phi = s @ Wphi_chunk : 16m x 64n warp tile, LDS.64 pair loads ----
  #pragma unroll 4
  for (int ks = 0; ks < 16; ks++){
    const int kp = ks * 8 + kb * 2;
    uint2 a0 = *(const uint2*)(su + OFF_S + (rA0    )*136 + kp);
    uint2 a1 = *(const uint2*)(su + OFF_S + (rA0 + 8)*136 + kp);
    #pragma unroll
    for (int nt = 0; nt < 8; nt++){
      const int n = nb + nt * 8 + qr;
      uint2 b = *(const uint2*)(su + OFF_B + n*136 + kp);
      mma8(acc[nt], a0.x, a1.x, a0.y, a1.y, b.x, b.y);
    }
  }

  // ---- rbf fragments (K padded 20->24) ----
  uint32_t ra[3][4];
  #pragma unroll
  for (int ks = 0; ks < 3; ks++){
    const int k = ks * 8 + kb;
    ra[ks][0] = su[OFF_RBF + rA0*28 + k];
    ra[ks][1] = su[OFF_RBF + (rA0+8)*28 + k];
    ra[ks][2] = su[OFF_RBF + rA0*28 + k + 4];
    ra[ks][3] = su[OFF_RBF + (rA0+8)*28 + k + 4];
  }

  const bool even = (kb & 1) == 0;
  const int rowT  = mg*16 + qr + (even ? 0 : 8);
  const int eT    = eb + rowT;
  const int node  = ((const int*)(smf + OFF_IDX))[rowT];
  float rx = 0.f, ry = 0.f, rz = 0.f;
  if (MODE == 2){
    rx = smf[OFF_RN + rowT*4 + 0];
    ry = smf[OFF_RN + rowT*4 + 1];
    rz = smf[OFF_RN + rowT*4 + 2];
  }
  const int cb0 = (kb >> 1) * 4;      // merged col base within n-tile

  #pragma unroll
  for (int nt = 0; nt < 8; nt++){
    const int n = nb + nt * 8 + qr;
    const int cc = nb + nt * 8 + 2 * kb;
    const float2 bp = *(const float2*)(bphi_g + c*F + cc);
    const float2 bw = *(const float2*)(bw_g   + c*F + cc);
    // w = rbf @ Ww_chunk
    float w4[4] = {0.f, 0.f, 0.f, 0.f};
    #pragma unroll
    for (int ks = 0; ks < 3; ks++){
      const int k = ks * 8 + kb;
      uint32_t wb0 = su[OFF_WW + (c*128 + n)*28 + k];
      uint32_t wb1 = su[OFF_WW + (c*128 + n)*28 + k + 4];
      mma8(w4, ra[ks][0], ra[ks][1], ra[ks][2], ra[ks][3], wb0, wb1);
    }
    float s0 = (w4[0] + bw.x) * (acc[nt][0] + bp.x);
    float s1 = (w4[1] + bw.y) * (acc[nt][1] + bp.y);
    float s2 = (w4[2] + bw.x) * (acc[nt][2] + bp.x);
    float s3 = (w4[3] + bw.y) * (acc[nt][3] + bp.y);

    if (MODE == 0){
      sv[nt][0] = s0; sv[nt][1] = s1; sv[nt][2] = s2; sv[nt][3] = s3;
    } else if (MODE == 1){
      float x0 = __shfl_xor_sync(0xffffffffu, s0, 1);
      float x1 = __shfl_xor_sync(0xffffffffu, s1, 1);
      float x2 = __shfl_xor_sync(0xffffffffu, s2, 1);
      float x3 = __shfl_xor_sync(0xffffffffu, s3, 1);
      float q0 = even ? s0 : x2, q1 = even ? s1 : x3;
      float q2 = even ? x0 : s2, q3 = even ? x1 : s3;
      if (eT < E)
        red4(out_s + (size_t)node*F + nb + nt*8 + cb0, q0, q1, q2, q3);
    } else {
      float* svp = sv[nt];
      float y0 = __shfl_xor_sync(0xffffffffu, svp[0], 1);
      float y1 = __shfl_xor_sync(0xffffffffu, svp[1], 1);
      float y2 = __shfl_xor_sync(0xffffffffu, svp[2], 1);
      float y3 = __shfl_xor_sync(0xffffffffu, svp[3], 1);
      float x0 = __shfl_xor_sync(0xffffffffu, s0, 1);
      float x1 = __shfl_xor_sync(0xffffffffu, s1, 1);
      float x2 = __shfl_xor_sync(0xffffffffu, s2, 1);
      float x3 = __shfl_xor_sync(0xffffffffu, s3, 1);
      float pv0 = even ? svp[0] : y2, pv1 = even ? svp[1] : y3;
      float pv2 = even ? y0 : svp[2], pv3 = even ? y1 : svp[3];
      float pr0 = even ? s0 : x2, pr1 = even ? s1 : x3;
      float pr2 = even ? x0 : s2, pr3 = even ? x1 : s3;
      if (eT < E){
        const float* vp = v_g   + (size_t)eT   * 3*F + nb + nt*8 + cb0;
        float*       op = out_v + (size_t)node * 3*F + nb + nt*8 + cb0;
        #pragma unroll
        for (int d = 0; d < 3; d++){
          const float rd = (d == 0) ? rx : (d == 1) ? ry : rz;
          const float4 vv = *(const float4*)(vp + d*F);
          red4(op + d*F,
               fmaf(pv0, vv.x, pr0*rd), fmaf(pv1, vv.y, pr1*rd),
               fmaf(pv2, vv.z, pr2*rd), fmaf(pv3, vv.w, pr3*rd));
        }
      }
    }
  }
}

static __device__ __forceinline__ void stage_B(uint32_t* __restrict__ su,
    const float* __restrict__ Wp_g, int c, int tid){
  #pragma unroll 8
  for (int it = 0; it < 32; it++){
    int i = it * NTHREADS + tid;       // 16384 elements, coalesced over n
    int kk = i >> 7, n = i & 127;
    su[OFF_B + n*136 + pairpos(kk)] = to_tf32(Wp_g[kk*384 + c*128 + n]);
  }
}

__global__ void __launch_bounds__(NTHREADS, 1)
fused_message_kernel(
    const float* __restrict__ s_g, const float* __restrict__ r_g,
    const float* __restrict__ v_g, const int*   __restrict__ idx_g,
    const float* __restrict__ Wp_g, const float* __restrict__ bphi_g,
    const float* __restrict__ Ww_g, const float* __restrict__ bw_g,
    float* __restrict__ out_v, float* __restrict__ out_s, int E)
{
  extern __shared__ float smf[];
  uint32_t* su = (uint32_t*)smf;
  const int tid  = threadIdx.x;
  const int wid  = tid >> 5;
  const int lane = tid & 31;
  const int eb   = blockIdx.x * TM;

  // ---- prologue ----
  if (wid == 0){
    float gs = 0.f;
    #pragma unroll
    for (int j = 0; j < 16; j++) gs += g_part[lane + 32*j];
    #pragma unroll
    for (int o = 16; o > 0; o >>= 1) gs += __shfl_xor_sync(0xffffffffu, gs, o);
    if (lane == 0) smf[OFF_G] = rsqrtf(gs);
  }
  // s tile -> tf32 [128][136] interleaved
  {
    const float4* s4 = (const float4*)s_g;
    #pragma unroll
    for (int it = 0; it < 8; it++){
      int i = it * NTHREADS + tid;      // 4096 float4
      int m = i >> 5, q = i & 31;
      float4 val = make_float4(0.f, 0.f, 0.f, 0.f);
      if (eb + m < E) val = s4[(size_t)(eb + m) * 32 + q];
      int base = m*136 + (q >> 1)*8 + (q & 1);   // pairpos(4q + j) = base + 2j
      su[OFF_S + base + 0] = to_tf32(val.x);
      su[OFF_S + base + 2] = to_tf32(val.y);
      su[OFF_S + base + 4] = to_tf32(val.z);
      su[OFF_S + base + 6] = to_tf32(val.w);
    }
  }
  // zero k=20..23 pads of rbf and Ww (direct layouts)
  if (tid < 128) *(float4*)(smf + OFF_RBF + tid*28 + 20) = make_float4(0.f,0.f,0.f,0.f);
  for (int i = tid; i < 384; i += NTHREADS)
    *(float4*)(smf + OFF_WW + i*28 + 20) = make_float4(0.f,0.f,0.f,0.f);
  // Ww -> [3][128n][28k]
  for (int i = tid; i < NRBF * 384; i += NTHREADS){
    int kk = i / 384, gg = i % 384;
    int c = gg >> 7, n = gg & 127;
    su[OFF_WW + (c*128 + n)*28 + kk] = to_tf32(Ww_g[i]);
  }
  __syncthreads();   // g ready
  // rbf / rn / idx
  if (tid < TM){
    int ee = eb + tid;
    float rxv = 0.f, ryv = 0.f, rzv = 0.f;
    int node = 0;
    if (ee < E){
      rxv = r_g[3*ee+0]; ryv = r_g[3*ee+1]; rzv = r_g[3*ee+2];
      node = idx_g[ee];
    }
    ((int*)(smf + OFF_IDX))[tid] = node;
    float rn = sqrtf(fmaf(rxv,rxv, fmaf(ryv,ryv, rzv*rzv)));
    float invg = smf[OFF_G];
    smf[OFF_RN + tid*4+0] = rxv*invg;
    smf[OFF_RN + tid*4+1] = ryv*invg;
    smf[OFF_RN + tid*4+2] = rzv*invg;
    smf[OFF_RN + tid*4+3] = 0.f;
    if (ee < E){
      float inv_rn = 1.f / rn;
      const float c0 = 0.62831853071795864769f;  // pi / R_CUT
      #pragma unroll
      for (int k = 0; k < NRBF; k++){
        float t  = sinf((float)(k+1) * c0 * rn) * inv_rn;
        float rb = (t <= 5.0f) ? 0.5f*(cosf(c0*t) + 1.f) : 0.f;
        su[OFF_RBF + tid*28 + k] = to_tf32(rb);
      }
    } else {
      #pragma unroll
      for (int k = 0; k < NRBF; k++) su[OFF_RBF + tid*28 + k] = 0u;
    }
  }

  float sv[8][4];

  // chunk c=1 -> out_s
  stage_B(su, Wp_g, 1, tid);
  __syncthreads();
  run_chunk<1>(su, smf, wid, lane, eb, E, 1, bphi_g, bw_g, v_g, out_s, out_v, sv);
  __syncthreads();
  // chunk c=0 -> sv (registers)
  stage_B(su, Wp_g, 0, tid);
  __syncthreads();
  run_chunk<0>(su, smf, wid, lane, eb, E, 0, bphi_g, bw_g, v_g, out_s, out_v, sv);
  __syncthreads();
  // chunk c=2 -> sr, combine with sv and v -> out_v
  stage_B(su, Wp_g, 2, tid);
  __syncthreads();
  run_chunk<2>(su, smf, wid, lane, eb, E, 2, bphi_g, bw_g, v_g, out_s, out_v, sv);
}

extern "C" void kernel_launch(void* const* d_in, const int* in_sizes, int n_in,
                              void* d_out, int out_size){
  const float* s_g  = (const float*)d_in[0];
  const float* r_g  = (const float*)d_in[1];
  const float* v_g  = (const float*)d_in[2];
  const int*   idx  = (const int*)  d_in[3];
  const float* Wp   = (const float*)d_in[4];
  const float* bphi = (const float*)d_in[5];
  const float* Ww   = (const float*)d_in[6];
  const float* bw   = (const float*)d_in[7];
  const int E = in_sizes[1] / 3;            // r is (E,3)
  const int N = out_size / (4*F);           // out = out_v (N*3*F) ++ out_s (N*F)
  float* out_v = (float*)d_out;
  float* out_s = out_v + (size_t)N*3*F;

  reduce_zero_kernel<<<512, 256>>>(r_g, 3*E, (float4*)d_out, out_size/4);
  cudaFuncSetAttribute(fused_message_kernel,
                       cudaFuncAttributeMaxDynamicSharedMemorySize, SMEM_BYTES);
  const int blocks = (E + TM - 1) / TM;
  fused_message_kernel<<<blocks, NTHREADS, SMEM_BYTES>>>(
      s_g, r_g, v_g, idx, Wp, bphi, Ww, bw, out_v, out_s, E);
}

// round 8
// speedup vs baseline: 1.1089x; 1.0254x over previous
#include <cuda_runtime.h>
#include <cstdint>

#define F        128
#define TM       64
#define NTHREADS 256
#define NRBF     20

// smem offsets in FLOATS (per CTA ~76KB -> 2 CTAs/SM)
#define OFF_S    0            // s tile [64][136] k-pair interleaved    8704
#define OFF_B    8704         // W_phi (chunk, n-half) [64n][136]       8704
#define OFF_RBF  17408        // rbf [64][20] direct                    1280
#define OFF_IDX  18688        // 64 ints
#define OFF_RN   18752        // 64 * 4 floats
#define OFF_G    19008        // 1 float: rsqrt(frobenius^2)
#define SMEM_FLOATS 19016
#define SMEM_BYTES  (SMEM_FLOATS * 4)

__device__ float g_part[512];

static __device__ __forceinline__ uint32_t to_tf32(float x){
  uint32_t t;
  asm("cvt.rna.tf32.f32 %0, %1;" : "=r"(t) : "f"(x));
  return t;
}
static __device__ __forceinline__ void mma8(float c[4], uint32_t a0, uint32_t a1,
    uint32_t a2, uint32_t a3, uint32_t b0, uint32_t b1){
  asm volatile("mma.sync.aligned.m16n8k8.row.col.f32.tf32.tf32.f32 "
    "{%0,%1,%2,%3}, {%4,%5,%6,%7}, {%8,%9}, {%0,%1,%2,%3};"
    : "+f"(c[0]), "+f"(c[1]), "+f"(c[2]), "+f"(c[3])
    : "r"(a0), "r"(a1), "r"(a2), "r"(a3), "r"(b0), "r"(b1));
}
static __device__ __forceinline__ void red4(float* p, float a, float b, float c, float d){
  asm volatile("red.global.add.v4.f32 [%0], {%1, %2, %3, %4};"
               :: "l"(p), "f"(a), "f"(b), "f"(c), "f"(d) : "memory");
}

__global__ void reduce_zero_kernel(const float* __restrict__ r, int n,
                                   float4* __restrict__ out4, int nout4){
  for (int i = blockIdx.x * blockDim.x + threadIdx.x; i < nout4; i += gridDim.x * blockDim.x)
    out4[i] = make_float4(0.f, 0.f, 0.f, 0.f);
  float s = 0.f;
  for (int i = blockIdx.x * blockDim.x + threadIdx.x; i < n; i += gridDim.x * blockDim.x){
    float x = r[i];
    s = fmaf(x, x, s);
  }
  #pragma unroll
  for (int o = 16; o > 0; o >>= 1) s += __shfl_xor_sync(0xffffffffu, s, o);
  __shared__ float ws[8];
  int lane = threadIdx.x & 31, w = threadIdx.x >> 5;
  if (lane == 0) ws[w] = s;
  __syncthreads();
  if (threadIdx.x < 32){
    s = (threadIdx.x < 8) ? ws[threadIdx.x] : 0.f;
    #pragma unroll
    for (int o = 4; o > 0; o >>= 1) s += __shfl_xor_sync(0xffffffffu, s, o);
    if (threadIdx.x == 0) g_part[blockIdx.x] = s;
  }
}

// stage one (chunk c, n-half nh) of W_phi into the B buffer: STS.64 pair stores
static __device__ __forceinline__ void stage_B(uint32_t* __restrict__ su,
    const float* __restrict__ Wp_g, int c, int nh, int tid){
  #pragma unroll
  for (int it = 0; it < 16; it++){
    int i = it * NTHREADS + tid;       // 4096 pairs
    int n  = i & 63;
    int kp = i >> 6;                   // 0..63
    int g  = kp >> 2, a = kp & 3;
    int k  = g * 8 + a;
    const float* src = Wp_g + (size_t)k * 384 + c * 128 + nh * 64 + n;
    uint2 st;
    st.x = to_tf32(src[0]);
    st.y = to_tf32(src[4 * 384]);
    *(uint2*)(su + OFF_B + n*136 + g*8 + a*2) = st;
  }
}

// MODE 0: store gated c=0 (sv) in regs; MODE 1: scatter out_s; MODE 2: combine -> out_v
template<int MODE>
static __device__ __forceinline__ void run_chunk(
    const uint32_t* __restrict__ su, const float* __restrict__ smf,
    int wid, int lane, int eb, int E, int c, int nh,
    const float* __restrict__ bphi_g, const float* __restrict__ bw_g,
    const float* __restrict__ Ww_g, const float* __restrict__ v_g,
    float* __restrict__ out_s, float* __restrict__ out_v,
    float (*sv)[4])
{
  const int mg  = wid >> 1;           // m-group: 16 edges
  const int nq  = wid & 1;            // n quarter within this half (32 cols)
  const int qr  = lane >> 2;
  const int kb  = lane & 3;
  const int rA0 = mg * 16 + qr;

  float acc[4][4];
  #pragma unroll
  for (int nt = 0; nt < 4; nt++){
    acc[nt][0]=0.f; acc[nt][1]=0.f; acc[nt][2]=0.f; acc[nt][3]=0.f;
  }

  // ---- phi = s @ Wphi(c, nh) : 16m x 32n warp tile, LDS.64 pair loads ----
  #pragma unroll 4
  for (int ks = 0; ks < 16; ks++){
    const int kp = ks * 8 + kb * 2;
    uint2 a0 = *(const uint2*)(su + OFF_S + (rA0    )*136 + kp);
    uint2 a1 = *(const uint2*)(su + OFF_S + (rA0 + 8)*136 + kp);
    #pragma unroll
    for (int nt = 0; nt < 4; nt++){
      const int nloc = nq*32 + nt*8 + qr;
      uint2 b = *(const uint2*)(su + OFF_B + nloc*136 + kp);
      mma8(acc[nt], a0.x, a1.x, a0.y, a1.y, b.x, b.y);
    }
  }

  // ---- rbf fragments (K = 20, k>=20 contributes zero) ----
  uint32_t ra[3][4];
  #pragma unroll
  for (int ks = 0; ks < 3; ks++){
    const int k = ks * 8 + kb;
    ra[ks][0] = su[OFF_RBF + rA0*20 + k];
    ra[ks][1] = su[OFF_RBF + (rA0+8)*20 + k];
    if (ks < 2){
      ra[ks][2] = su[OFF_RBF + rA0*20 + k + 4];
      ra[ks][3] = su[OFF_RBF + (rA0+8)*20 + k + 4];
    } else {
      ra[ks][2] = 0u; ra[ks][3] = 0u;
    }
  }

  const bool even = (kb & 1) == 0;
  const int rowT  = mg*16 + qr + (even ? 0 : 8);
  const int eT    = eb + rowT;
  const int node  = ((const int*)(smf + OFF_IDX))[rowT];
  float rx = 0.f, ry = 0.f, rz = 0.f;
  if (MODE == 2){
    rx = smf[OFF_RN + rowT*4 + 0];
    ry = smf[OFF_RN + rowT*4 + 1];
    rz = smf[OFF_RN + rowT*4 + 2];
  }
  const int cb0 = (kb >> 1) * 4;      // merged col base within n-tile

  #pragma unroll
  for (int nt = 0; nt < 4; nt++){
    const int ncol = nh*64 + nq*32 + nt*8 + qr;
    const int cc   = nh*64 + nq*32 + nt*8 + 2*kb;
    const float2 bp = *(const float2*)(bphi_g + c*F + cc);
    const float2 bw = *(const float2*)(bw_g   + c*F + cc);
    // w = rbf @ Ww_chunk : B fragments straight from gmem (L1-resident, 30KB)
    float w4[4] = {0.f, 0.f, 0.f, 0.f};
    #pragma unroll
    for (int ks = 0; ks < 3; ks++){
      const int k = ks * 8 + kb;
      uint32_t wb0 = to_tf32(__ldg(Ww_g + (size_t)k*384 + c*128 + ncol));
      uint32_t wb1 = (ks < 2) ? to_tf32(__ldg(Ww_g + (size_t)(k+4)*384 + c*128 + ncol)) : 0u;
      mma8(w4, ra[ks][0], ra[ks][1], ra[ks][2], ra[ks][3], wb0, wb1);
    }
    float s0 = (w4[0] + bw.x) * (acc[nt][0] + bp.x);
    float s1 = (w4[1] + bw.y) * (acc[nt][1] + bp.y);
    float s2 = (w4[2] + bw.x) * (acc[nt][2] + bp.x);
    float s3 = (w4[3] + bw.y) * (acc[nt][3] + bp.y);

    if (MODE == 0){
      sv[nt][0] = s0; sv[nt][1] = s1; sv[nt][2] = s2; sv[nt][3] = s3;
    } else if (MODE == 1){
      float x0 = __shfl_xor_sync(0xffffffffu, s0, 1);
      float x1 = __shfl_xor_sync(0xffffffffu, s1, 1);
      float x2 = __shfl_xor_sync(0xffffffffu, s2, 1);
      float x3 = __shfl_xor_sync(0xffffffffu, s3, 1);
      float q0 = even ? s0 : x2, q1 = even ? s1 : x3;
      float q2 = even ? x0 : s2, q3 = even ? x1 : s3;
      if (eT < E)
        red4(out_s + (size_t)node*F + nh*64 + nq*32 + nt*8 + cb0, q0, q1, q2, q3);
    } else {
      float* svp = sv[nt];
      float y0 = __shfl_xor_sync(0xffffffffu, svp[0], 1);
      float y1 = __shfl_xor_sync(0xffffffffu, svp[1], 1);
      float y2 = __shfl_xor_sync(0xffffffffu, svp[2], 1);
      float y3 = __shfl_xor_sync(0xffffffffu, svp[3], 1);
      float x0 = __shfl_xor_sync(0xffffffffu, s0, 1);
      float x1 = __shfl_xor_sync(0xffffffffu, s1, 1);
      float x2 = __shfl_xor_sync(0xffffffffu, s2, 1);
      float x3 = __shfl_xor_sync(0xffffffffu, s3, 1);
      float pv0 = even ? svp[0] : y2, pv1 = even ? svp[1] : y3;
      float pv2 = even ? y0 : svp[2], pv3 = even ? y1 : svp[3];
      float pr0 = even ? s0 : x2, pr1 = even ? s1 : x3;
      float pr2 = even ? x0 : s2, pr3 = even ? x1 : s3;
      if (eT < E){
        const int colb = nh*64 + nq*32 + nt*8 + cb0;
        const float* vp = v_g   + (size_t)eT   * 3*F + colb;
        float*       op = out_v + (size_t)node * 3*F + colb;
        #pragma unroll
        for (int d = 0; d < 3; d++){
          const float rd = (d == 0) ? rx : (d == 1) ? ry : rz;
          const float4 vv = *(const float4*)(vp + d*F);
          red4(op + d*F,
               fmaf(pv0, vv.x, pr0*rd), fmaf(pv1, vv.y, pr1*rd),
               fmaf(pv2, vv.z, pr2*rd), fmaf(pv3, vv.w, pr3*rd));
        }
      }
    }
  }
}

__global__ void __launch_bounds__(NTHREADS, 2)
fused_message_kernel(
    const float* __restrict__ s_g, const float* __restrict__ r_g,
    const float* __restrict__ v_g, const int*   __restrict__ idx_g,
    const float* __restrict__ Wp_g, const float* __restrict__ bphi_g,
    const float* __restrict__ Ww_g, const float* __restrict__ bw_g,
    float* __restrict__ out_v, float* __restrict__ out_s, int E)
{
  extern __shared__ float smf[];
  uint32_t* su = (uint32_t*)smf;
  const int tid  = threadIdx.x;
  const int wid  = tid >> 5;
  const int lane = tid & 31;
  const int eb   = blockIdx.x * TM;

  // ---- prologue ----
  if (wid == 0){
    float gs = 0.f;
    #pragma unroll
    for (int j = 0; j < 16; j++) gs += g_part[lane + 32*j];
    #pragma unroll
    for (int o = 16; o > 0; o >>= 1) gs += __shfl_xor_sync(0xffffffffu, gs, o);
    if (lane == 0) smf[OFF_G] = rsqrtf(gs);
  }
  // s tile -> tf32 [64][136] interleaved, STS.128 stores (8-k groups)
  {
    const uint4* s4 = (const uint4*)s_g;
    #pragma unroll
    for (int it = 0; it < 4; it++){
      int i = it * NTHREADS + tid;      // 1024 8-k groups
      int m = i >> 4, j = i & 15;
      uint4 A0 = make_uint4(0u,0u,0u,0u), A1 = make_uint4(0u,0u,0u,0u);
      if (eb + m < E){
        A0 = s4[(size_t)(eb + m) * 32 + 2*j];
        A1 = s4[(size_t)(eb + m) * 32 + 2*j + 1];
      }
      uint4 t0, t1;
      t0.x = to_tf32(__uint_as_float(A0.x)); t0.y = to_tf32(__uint_as_float(A1.x));
      t0.z = to_tf32(__uint_as_float(A0.y)); t0.w = to_tf32(__uint_as_float(A1.y));
      t1.x = to_tf32(__uint_as_float(A0.z)); t1.y = to_tf32(__uint_as_float(A1.z));
      t1.z = to_tf32(__uint_as_float(A0.w)); t1.w = to_tf32(__uint_as_float(A1.w));
      *(uint4*)(su + OFF_S + m*136 + 8*j)     = t0;
      *(uint4*)(su + OFF_S + m*136 + 8*j + 4) = t1;
    }
  }
  __syncthreads();   // g ready; s staged
  // rbf / rn / idx (phase shared with first B staging)
  if (tid < TM){
    int ee = eb + tid;
    float rxv = 0.f, ryv = 0.f, rzv = 0.f;
    int node = 0;
    if (ee < E){
      rxv = r_g[3*ee+0]; ryv = r_g[3*ee+1]; rzv = r_g[3*ee+2];
      node = idx_g[ee];
    }
    ((int*)(smf + OFF_IDX))[tid] = node;
    float rn = sqrtf(fmaf(rxv,rxv, fmaf(ryv,ryv, rzv*rzv)));
    float invg = smf[OFF_G];
    smf[OFF_RN + tid*4+0] = rxv*invg;
    smf[OFF_RN + tid*4+1] = ryv*invg;
    smf[OFF_RN + tid*4+2] = rzv*invg;
    smf[OFF_RN + tid*4+3] = 0.f;
    if (ee < E){
      float inv_rn = 1.f / rn;
      const float c0 = 0.62831853071795864769f;  // pi / R_CUT
      #pragma unroll
      for (int k = 0; k < NRBF; k++){
        float t  = sinf((float)(k+1) * c0 * rn) * inv_rn;
        float rb = (t <= 5.0f) ? 0.5f*(cosf(c0*t) + 1.f) : 0.f;
        su[OFF_RBF + tid*20 + k] = to_tf32(rb);
      }
    } else {
      #pragma unroll
      for (int k = 0; k < NRBF; k++) su[OFF_RBF + tid*20 + k] = 0u;
    }
  }
  stage_B(su, Wp_g, 1, 0, tid);
  __syncthreads();

  float sv[4][4];

  #pragma unroll
  for (int nh = 0; nh < 2; nh++){
    // chunk c=1 -> out_s
    run_chunk<1>(su, smf, wid, lane, eb, E, 1, nh, bphi_g, bw_g, Ww_g, v_g, out_s, out_v, sv);
    __syncthreads();
    stage_B(su, Wp_g, 0, nh, tid);
    __syncthreads();
    // chunk c=0 -> sv (registers)
    run_chunk<0>(su, smf, wid, lane, eb, E, 0, nh, bphi_g, bw_g, Ww_g, v_g, out_s, out_v, sv);
    __syncthreads();
    stage_B(su, Wp_g, 2, nh, tid);
    __syncthreads();
    // chunk c=2 -> sr, combine with sv and v -> out_v
    run_chunk<2>(su, smf, wid, lane, eb, E, 2, nh, bphi_g, bw_g, Ww_g, v_g, out_s, out_v, sv);
    __syncthreads();
    if (nh == 0){
      stage_B(su, Wp_g, 1, 1, tid);
      __syncthreads();
    }
  }
}

extern "C" void kernel_launch(void* const* d_in, const int* in_sizes, int n_in,
                              void* d_out, int out_size){
  const float* s_g  = (const float*)d_in[0];
  const float* r_g  = (const float*)d_in[1];
  const float* v_g  = (const float*)d_in[2];
  const int*   idx  = (const int*)  d_in[3];
  const float* Wp   = (const float*)d_in[4];
  const float* bphi = (const float*)d_in[5];
  const float* Ww   = (const float*)d_in[6];
  const float* bw   = (const float*)d_in[7];
  const int E = in_sizes[1] / 3;            // r is (E,3)
  const int N = out_size / (4*F);           // out = out_v (N*3*F) ++ out_s (N*F)
  float* out_v = (float*)d_out;
  float* out_s = out_v + (size_t)N*3*F;

  reduce_zero_kernel<<<512, 256>>>(r_g, 3*E, (float4*)d_out, out_size/4);
  cudaFuncSetAttribute(fused_message_kernel,
                       cudaFuncAttributeMaxDynamicSharedMemorySize, SMEM_BYTES);
  const int blocks = (E + TM - 1) / TM;
  fused_message_kernel<<<blocks, NTHREADS, SMEM_BYTES>>>(
      s_g, r_g, v_g, idx, Wp, bphi, Ww, bw, out_v, out_s, E);
}

// round 9
// speedup vs baseline: 1.4825x; 1.3369x over previous
#include <cuda_runtime.h>
#include <cstdint>

#define F        128
#define TM       64
#define NTHREADS 256
#define NRBF     20

// smem offsets in FLOATS (~74KB per CTA -> 2 CTAs/SM)
#define OFF_S    0            // s tile [64][136] k-pair interleaved    8704
#define OFF_RBF  8704         // rbf [64][20] direct                    1280
#define OFF_IDX  9984         // 64 ints
#define OFF_RN   10048        // 64 * 4 floats
#define OFF_G    10304        // 1 float (+3 pad)
#define OFF_SV   10308        // sv spill: [8][256] float4              8192
#define SMEM_FLOATS 18500
#define SMEM_BYTES  (SMEM_FLOATS * 4)

__device__ float g_part[512];
// fragment-major packed weights (built once per launch by reduce kernel)
//   wt_phi[((c*16 + ks)*16 + ntile)*32 + lane] = {W[k][c*128+n], W[k+4][c*128+n]}
__device__ uint2 wt_phi[3 * 16 * 16 * 32];
//   wt_ww [((c*3  + ks)*16 + ntile)*32 + lane]
__device__ uint2 wt_ww [3 * 3 * 16 * 32];

static __device__ __forceinline__ uint32_t to_tf32(float x){
  uint32_t t;
  asm("cvt.rna.tf32.f32 %0, %1;" : "=r"(t) : "f"(x));
  return t;
}
static __device__ __forceinline__ void mma8(float c[4], uint32_t a0, uint32_t a1,
    uint32_t a2, uint32_t a3, uint32_t b0, uint32_t b1){
  asm volatile("mma.sync.aligned.m16n8k8.row.col.f32.tf32.tf32.f32 "
    "{%0,%1,%2,%3}, {%4,%5,%6,%7}, {%8,%9}, {%0,%1,%2,%3};"
    : "+f"(c[0]), "+f"(c[1]), "+f"(c[2]), "+f"(c[3])
    : "r"(a0), "r"(a1), "r"(a2), "r"(a3), "r"(b0), "r"(b1));
}
static __device__ __forceinline__ void red4(float* p, float a, float b, float c, float d){
  asm volatile("red.global.add.v4.f32 [%0], {%1, %2, %3, %4};"
               :: "l"(p), "f"(a), "f"(b), "f"(c), "f"(d) : "memory");
}

// zero output + frobenius partials + pack W_phi / W_w fragment-major
__global__ void prep_kernel(const float* __restrict__ r, int n,
                            float4* __restrict__ out4, int nout4,
                            const float* __restrict__ Wp_g,
                            const float* __restrict__ Ww_g){
  const int gtid = blockIdx.x * blockDim.x + threadIdx.x;
  const int gstr = gridDim.x * blockDim.x;
  for (int i = gtid; i < nout4; i += gstr)
    out4[i] = make_float4(0.f, 0.f, 0.f, 0.f);
  // W_phi fragments
  for (int i = gtid; i < 3*16*16*32; i += gstr){
    int l = i & 31, t = (i >> 5) & 15, ks = (i >> 9) & 15, c = i >> 13;
    int qr = l >> 2, kb = l & 3;
    int nn = t*8 + qr, k = ks*8 + kb;
    uint2 val;
    val.x = to_tf32(Wp_g[(size_t)k    *384 + c*128 + nn]);
    val.y = to_tf32(Wp_g[(size_t)(k+4)*384 + c*128 + nn]);
    wt_phi[i] = val;
  }
  // W_w fragments (K=20; k+4 >= 20 -> 0)
  for (int i = gtid; i < 3*3*16*32; i += gstr){
    int l = i & 31, t = (i >> 5) & 15, rr = i >> 9;   // rr = c*3 + ks
    int ks = rr % 3, c = rr / 3;
    int qr = l >> 2, kb = l & 3;
    int nn = t*8 + qr, k = ks*8 + kb;
    uint2 val;
    val.x = to_tf32(Ww_g[(size_t)k*384 + c*128 + nn]);
    val.y = (k + 4 < NRBF) ? to_tf32(Ww_g[(size_t)(k+4)*384 + c*128 + nn]) : 0u;
    wt_ww[i] = val;
  }
  // frobenius sum of squares
  float s = 0.f;
  for (int i = gtid; i < n; i += gstr){
    float x = r[i];
    s = fmaf(x, x, s);
  }
  #pragma unroll
  for (int o = 16; o > 0; o >>= 1) s += __shfl_xor_sync(0xffffffffu, s, o);
  __shared__ float ws[8];
  int lane = threadIdx.x & 31, w = threadIdx.x >> 5;
  if (lane == 0) ws[w] = s;
  __syncthreads();
  if (threadIdx.x < 32){
    s = (threadIdx.x < 8) ? ws[threadIdx.x] : 0.f;
    #pragma unroll
    for (int o = 4; o > 0; o >>= 1) s += __shfl_xor_sync(0xffffffffu, s, o);
    if (threadIdx.x == 0) g_part[blockIdx.x] = s;
  }
}

// MODE 0: stash gated c=0 (sv) in smem; MODE 1: scatter out_s; MODE 2: combine -> out_v
template<int MODE>
static __device__ __forceinline__ void run_chunk(
    const uint32_t* __restrict__ su, float* __restrict__ smf,
    int tid, int eb, int E, int c,
    const float* __restrict__ bphi_g, const float* __restrict__ bw_g,
    const float* __restrict__ v_g,
    float* __restrict__ out_s, float* __restrict__ out_v)
{
  const int wid  = tid >> 5;
  const int lane = tid & 31;
  const int mg   = wid >> 1;          // m-group: 16 edges
  const int nq   = wid & 1;           // n half (64 cols)
  const int qr   = lane >> 2;
  const int kb   = lane & 3;
  const int rA0  = mg * 16 + qr;
  const int nb   = nq * 64;

  float acc[8][4];
  #pragma unroll
  for (int nt = 0; nt < 8; nt++){
    acc[nt][0]=0.f; acc[nt][1]=0.f; acc[nt][2]=0.f; acc[nt][3]=0.f;
  }

  // ---- phi = s @ Wphi(c) : 16m x 64n warp tile; B fragments coalesced from gmem ----
  const uint2* wtp = wt_phi + ((size_t)c*16*16 + nq*8)*32 + lane;
  #pragma unroll 4
  for (int ks = 0; ks < 16; ks++){
    const int kp = ks * 8 + kb * 2;
    uint2 a0 = *(const uint2*)(su + OFF_S + (rA0    )*136 + kp);
    uint2 a1 = *(const uint2*)(su + OFF_S + (rA0 + 8)*136 + kp);
    const uint2* bptr = wtp + (size_t)ks*16*32;
    #pragma unroll
    for (int nt = 0; nt < 8; nt++){
      uint2 b = __ldg(bptr + nt*32);
      mma8(acc[nt], a0.x, a1.x, a0.y, a1.y, b.x, b.y);
    }
  }

  // ---- rbf fragments (K = 20, conflict-free [64][20] layout) ----
  uint32_t ra[3][4];
  #pragma unroll
  for (int ks = 0; ks < 3; ks++){
    const int k = ks * 8 + kb;
    ra[ks][0] = su[OFF_RBF + rA0*20 + k];
    ra[ks][1] = su[OFF_RBF + (rA0+8)*20 + k];
    if (ks < 2){
      ra[ks][2] = su[OFF_RBF + rA0*20 + k + 4];
      ra[ks][3] = su[OFF_RBF + (rA0+8)*20 + k + 4];
    } else {
      ra[ks][2] = 0u; ra[ks][3] = 0u;
    }
  }

  const bool even = (kb & 1) == 0;
  const int rowT  = mg*16 + qr + (even ? 0 : 8);
  const int eT    = eb + rowT;
  const int node  = ((const int*)(smf + OFF_IDX))[rowT];
  float rx = 0.f, ry = 0.f, rz = 0.f;
  if (MODE == 2){
    rx = smf[OFF_RN + rowT*4 + 0];
    ry = smf[OFF_RN + rowT*4 + 1];
    rz = smf[OFF_RN + rowT*4 + 2];
  }
  const int cb0 = (kb >> 1) * 4;      // merged col base within n-tile

  const uint2* wwp = wt_ww + ((size_t)c*3*16 + nq*8)*32 + lane;

  #pragma unroll
  for (int nt = 0; nt < 8; nt++){
    const int cc = nb + nt*8 + 2*kb;
    const float2 bp = *(const float2*)(bphi_g + c*F + cc);
    const float2 bw = *(const float2*)(bw_g   + c*F + cc);
    // w = rbf @ Ww_chunk : coalesced fragment loads
    float w4[4] = {0.f, 0.f, 0.f, 0.f};
    #pragma unroll
    for (int ks = 0; ks < 3; ks++){
      uint2 wb = __ldg(wwp + ((size_t)ks*16 + nt)*32);
      mma8(w4, ra[ks][0], ra[ks][1], ra[ks][2], ra[ks][3], wb.x, wb.y);
    }
    float s0 = (w4[0] + bw.x) * (acc[nt][0] + bp.x);
    float s1 = (w4[1] + bw.y) * (acc[nt][1] + bp.y);
    float s2 = (w4[2] + bw.x) * (acc[nt][2] + bp.x);
    float s3 = (w4[3] + bw.y) * (acc[nt][3] + bp.y);

    if (MODE == 0){
      *(float4*)(smf + OFF_SV + (nt*NTHREADS + tid)*4) = make_float4(s0, s1, s2, s3);
    } else if (MODE == 1){
      float x0 = __shfl_xor_sync(0xffffffffu, s0, 1);
      float x1 = __shfl_xor_sync(0xffffffffu, s1, 1);
      float x2 = __shfl_xor_sync(0xffffffffu, s2, 1);
      float x3 = __shfl_xor_sync(0xffffffffu, s3, 1);
      float q0 = even ? s0 : x2, q1 = even ? s1 : x3;
      float q2 = even ? x0 : s2, q3 = even ? x1 : s3;
      if (eT < E)
        red4(out_s + (size_t)node*F + nb + nt*8 + cb0, q0, q1, q2, q3);
    } else {
      const float4 svq = *(const float4*)(smf + OFF_SV + (nt*NTHREADS + tid)*4);
      float y0 = __shfl_xor_sync(0xffffffffu, svq.x, 1);
      float y1 = __shfl_xor_sync(0xffffffffu, svq.y, 1);
      float y2 = __shfl_xor_sync(0xffffffffu, svq.z, 1);
      float y3 = __shfl_xor_sync(0xffffffffu, svq.w, 1);
      float x0 = __shfl_xor_sync(0xffffffffu, s0, 1);
      float x1 = __shfl_xor_sync(0xffffffffu, s1, 1);
      float x2 = __shfl_xor_sync(0xffffffffu, s2, 1);
      float x3 = __shfl_xor_sync(0xffffffffu, s3, 1);
      float pv0 = even ? svq.x : y2, pv1 = even ? svq.y : y3;
      float pv2 = even ? y0 : svq.z, pv3 = even ? y1 : svq.w;
      float pr0 = even ? s0 : x2, pr1 = even ? s1 : x3;
      float pr2 = even ? x0 : s2, pr3 = even ? x1 : s3;
      if (eT < E){
        const int colb = nb + nt*8 + cb0;
        const float* vp = v_g   + (size_t)eT   * 3*F + colb;
        float*       op = out_v + (size_t)node * 3*F + colb;
        #pragma unroll
        for (int d = 0; d < 3; d++){
          const float rd = (d == 0) ? rx : (d == 1) ? ry : rz;
          const float4 vv = *(const float4*)(vp + d*F);
          red4(op + d*F,
               fmaf(pv0, vv.x, pr0*rd), fmaf(pv1, vv.y, pr1*rd),
               fmaf(pv2, vv.z, pr2*rd), fmaf(pv3, vv.w, pr3*rd));
        }
      }
    }
  }
}

__global__ void __launch_bounds__(NTHREADS, 2)
fused_message_kernel(
    const float* __restrict__ s_g, const float* __restrict__ r_g,
    const float* __restrict__ v_g, const int*   __restrict__ idx_g,
    const float* __restrict__ bphi_g, const float* __restrict__ bw_g,
    float* __restrict__ out_v, float* __restrict__ out_s, int E)
{
  extern __shared__ float smf[];
  uint32_t* su = (uint32_t*)smf;
  const int tid  = threadIdx.x;
  const int wid  = tid >> 5;
  const int lane = tid & 31;
  const int eb   = blockIdx.x * TM;

  // ---- prologue ----
  if (wid == 0){
    float gs = 0.f;
    #pragma unroll
    for (int j = 0; j < 16; j++) gs += g_part[lane + 32*j];
    #pragma unroll
    for (int o = 16; o > 0; o >>= 1) gs += __shfl_xor_sync(0xffffffffu, gs, o);
    if (lane == 0) smf[OFF_G] = rsqrtf(gs);
  }
  // s tile -> tf32 [64][136] interleaved, STS.128 stores (8-k groups)
  {
    const uint4* s4 = (const uint4*)s_g;
    #pragma unroll
    for (int it = 0; it < 4; it++){
      int i = it * NTHREADS + tid;      // 1024 8-k groups
      int m = i >> 4, j = i & 15;
      uint4 A0 = make_uint4(0u,0u,0u,0u), A1 = make_uint4(0u,0u,0u,0u);
      if (eb + m < E){
        A0 = s4[(size_t)(eb + m) * 32 + 2*j];
        A1 = s4[(size_t)(eb + m) * 32 + 2*j + 1];
      }
      uint4 t0, t1;
      t0.x = to_tf32(__uint_as_float(A0.x)); t0.y = to_tf32(__uint_as_float(A1.x));
      t0.z = to_tf32(__uint_as_float(A0.y)); t0.w = to_tf32(__uint_as_float(A1.y));
      t1.x = to_tf32(__uint_as_float(A0.z)); t1.y = to_tf32(__uint_as_float(A1.z));
      t1.z = to_tf32(__uint_as_float(A0.w)); t1.w = to_tf32(__uint_as_float(A1.w));
      *(uint4*)(su + OFF_S + m*136 + 8*j)     = t0;
      *(uint4*)(su + OFF_S + m*136 + 8*j + 4) = t1;
    }
  }
  __syncthreads();   // g ready
  // rbf / rn / idx
  if (tid < TM){
    int ee = eb + tid;
    float rxv = 0.f, ryv = 0.f, rzv = 0.f;
    int node = 0;
    if (ee < E){
      rxv = r_g[3*ee+0]; ryv = r_g[3*ee+1]; rzv = r_g[3*ee+2];
      node = idx_g[ee];
    }
    ((int*)(smf + OFF_IDX))[tid] = node;
    float rn = sqrtf(fmaf(rxv,rxv, fmaf(ryv,ryv, rzv*rzv)));
    float invg = smf[OFF_G];
    smf[OFF_RN + tid*4+0] = rxv*invg;
    smf[OFF_RN + tid*4+1] = ryv*invg;
    smf[OFF_RN + tid*4+2] = rzv*invg;
    smf[OFF_RN + tid*4+3] = 0.f;
    if (ee < E){
      float inv_rn = 1.f / rn;
      const float c0 = 0.62831853071795864769f;  // pi / R_CUT
      #pragma unroll
      for (int k = 0; k < NRBF; k++){
        float t  = sinf((float)(k+1) * c0 * rn) * inv_rn;
        float rb = (t <= 5.0f) ? 0.5f*(cosf(c0*t) + 1.f) : 0.f;
        su[OFF_RBF + tid*20 + k] = to_tf32(rb);
      }
    } else {
      #pragma unroll
      for (int k = 0; k < NRBF; k++) su[OFF_RBF + tid*20 + k] = 0u;
    }
  }
  __syncthreads();

  // chunks: no inter-chunk syncs needed (W operands come from gmem; sv slots thread-private)
  run_chunk<1>(su, smf, tid, eb, E, 1, bphi_g, bw_g, v_g, out_s, out_v);
  run_chunk<0>(su, smf, tid, eb, E, 0, bphi_g, bw_g, v_g, out_s, out_v);
  run_chunk<2>(su, smf, tid, eb, E, 2, bphi_g, bw_g, v_g, out_s, out_v);
}

extern "C" void kernel_launch(void* const* d_in, const int* in_sizes, int n_in,
                              void* d_out, int out_size){
  const float* s_g  = (const float*)d_in[0];
  const float* r_g  = (const float*)d_in[1];
  const float* v_g  = (const float*)d_in[2];
  const int*   idx  = (const int*)  d_in[3];
  const float* Wp   = (const float*)d_in[4];
  const float* bphi = (const float*)d_in[5];
  const float* Ww   = (const float*)d_in[6];
  const float* bw   = (const float*)d_in[7];
  const int E = in_sizes[1] / 3;            // r is (E,3)
  const int N = out_size / (4*F);           // out = out_v (N*3*F) ++ out_s (N*F)
  float* out_v = (float*)d_out;
  float* out_s = out_v + (size_t)N*3*F;

  prep_kernel<<<512, 256>>>(r_g, 3*E, (float4*)d_out, out_size/4, Wp, Ww);
  cudaFuncSetAttribute(fused_message_kernel,
                       cudaFuncAttributeMaxDynamicSharedMemorySize, SMEM_BYTES);
  const int blocks = (E + TM - 1) / TM;
  fused_message_kernel<<<blocks, NTHREADS, SMEM_BYTES>>>(
      s_g, r_g, v_g, idx, bphi, bw, out_v, out_s, E);
}

// round 10
// speedup vs baseline: 1.6159x; 1.0900x over previous
#include <cuda_runtime.h>
#include <cstdint>

#define F        128
#define TM       64
#define NTHREADS 256
#define NRBF     20
#define RSTR     136   // row stride (floats): == 8 mod 32 -> conflict-free fragment STS

// smem offsets in FLOATS (~111KB per CTA -> 2 CTAs/SM)
#define OFF_S    0            // s tile [64][136]            8704
#define OFF_P1   8704         // stash buf 1 [64][136]       8704
#define OFF_P2   17408        // stash buf 2 [64][136]       8704
#define OFF_RBF  26112        // rbf [64][20]                1280
#define OFF_IDX  27392        // 64 ints
#define OFF_RN   27456        // 64*4 floats
#define OFF_G    27712        // 1 float
#define SMEM_FLOATS 27716
#define SMEM_BYTES  (SMEM_FLOATS * 4)

__device__ float g_part[512];
// fragment-major packed weights (built once per launch by prep kernel)
//   wt_phi[((c*16 + ks)*16 + ntile)*32 + lane] = {W[k][c*128+n], W[k+4][c*128+n]}
__device__ uint2 wt_phi[3 * 16 * 16 * 32];
__device__ uint2 wt_ww [3 * 3 * 16 * 32];

static __device__ __forceinline__ uint32_t to_tf32(float x){
  uint32_t t;
  asm("cvt.rna.tf32.f32 %0, %1;" : "=r"(t) : "f"(x));
  return t;
}
static __device__ __forceinline__ void mma8(float c[4], uint32_t a0, uint32_t a1,
    uint32_t a2, uint32_t a3, uint32_t b0, uint32_t b1){
  asm volatile("mma.sync.aligned.m16n8k8.row.col.f32.tf32.tf32.f32 "
    "{%0,%1,%2,%3}, {%4,%5,%6,%7}, {%8,%9}, {%0,%1,%2,%3};"
    : "+f"(c[0]), "+f"(c[1]), "+f"(c[2]), "+f"(c[3])
    : "r"(a0), "r"(a1), "r"(a2), "r"(a3), "r"(b0), "r"(b1));
}
static __device__ __forceinline__ void red4(float* p, float a, float b, float c, float d){
  asm volatile("red.global.add.v4.f32 [%0], {%1, %2, %3, %4};"
               :: "l"(p), "f"(a), "f"(b), "f"(c), "f"(d) : "memory");
}

// zero output + frobenius partials + pack W_phi / W_w fragment-major
__global__ void prep_kernel(const float* __restrict__ r, int n,
                            float4* __restrict__ out4, int nout4,
                            const float* __restrict__ Wp_g,
                            const float* __restrict__ Ww_g){
  const int gtid = blockIdx.x * blockDim.x + threadIdx.x;
  const int gstr = gridDim.x * blockDim.x;
  for (int i = gtid; i < nout4; i += gstr)
    out4[i] = make_float4(0.f, 0.f, 0.f, 0.f);
  for (int i = gtid; i < 3*16*16*32; i += gstr){
    int l = i & 31, t = (i >> 5) & 15, ks = (i >> 9) & 15, c = i >> 13;
    int qr = l >> 2, kb = l & 3;
    int nn = t*8 + qr, k = ks*8 + kb;
    uint2 val;
    val.x = to_tf32(Wp_g[(size_t)k    *384 + c*128 + nn]);
    val.y = to_tf32(Wp_g[(size_t)(k+4)*384 + c*128 + nn]);
    wt_phi[i] = val;
  }
  for (int i = gtid; i < 3*3*16*32; i += gstr){
    int l = i & 31, t = (i >> 5) & 15, rr = i >> 9;   // rr = c*3 + ks
    int ks = rr % 3, c = rr / 3;
    int qr = l >> 2, kb = l & 3;
    int nn = t*8 + qr, k = ks*8 + kb;
    uint2 val;
    val.x = to_tf32(Ww_g[(size_t)k*384 + c*128 + nn]);
    val.y = (k + 4 < NRBF) ? to_tf32(Ww_g[(size_t)(k+4)*384 + c*128 + nn]) : 0u;
    wt_ww[i] = val;
  }
  float s = 0.f;
  for (int i = gtid; i < n; i += gstr){
    float x = r[i];
    s = fmaf(x, x, s);
  }
  #pragma unroll
  for (int o = 16; o > 0; o >>= 1) s += __shfl_xor_sync(0xffffffffu, s, o);
  __shared__ float ws[8];
  int lane = threadIdx.x & 31, w = threadIdx.x >> 5;
  if (lane == 0) ws[w] = s;
  __syncthreads();
  if (threadIdx.x < 32){
    s = (threadIdx.x < 8) ? ws[threadIdx.x] : 0.f;
    #pragma unroll
    for (int o = 4; o > 0; o >>= 1) s += __shfl_xor_sync(0xffffffffu, s, o);
    if (threadIdx.x == 0) g_part[blockIdx.x] = s;
  }
}

// compute chunk c, gate, stash into smem buffer at 'buf' (natural [row][col] layout)
static __device__ __forceinline__ void run_chunk(
    const uint32_t* __restrict__ su, float* __restrict__ smf,
    int tid, int c, int buf,
    const float* __restrict__ bphi_g, const float* __restrict__ bw_g)
{
  const int wid  = tid >> 5;
  const int lane = tid & 31;
  const int mg   = wid >> 1;          // m-group: 16 edges
  const int nq   = wid & 1;           // n half (64 cols)
  const int qr   = lane >> 2;
  const int kb   = lane & 3;
  const int rA0  = mg * 16 + qr;
  const int nb   = nq * 64;

  float acc[8][4];
  #pragma unroll
  for (int nt = 0; nt < 8; nt++){
    acc[nt][0]=0.f; acc[nt][1]=0.f; acc[nt][2]=0.f; acc[nt][3]=0.f;
  }

  // ---- phi = s @ Wphi(c) : 16m x 64n warp tile; B fragments coalesced from gmem ----
  const uint2* wtp = wt_phi + ((size_t)c*16*16 + nq*8)*32 + lane;
  #pragma unroll 4
  for (int ks = 0; ks < 16; ks++){
    const int kp = ks * 8 + kb * 2;
    uint2 a0 = *(const uint2*)(su + OFF_S + (rA0    )*RSTR + kp);
    uint2 a1 = *(const uint2*)(su + OFF_S + (rA0 + 8)*RSTR + kp);
    const uint2* bptr = wtp + (size_t)ks*16*32;
    #pragma unroll
    for (int nt = 0; nt < 8; nt++){
      uint2 b = __ldg(bptr + nt*32);
      mma8(acc[nt], a0.x, a1.x, a0.y, a1.y, b.x, b.y);
    }
  }

  // ---- rbf fragments (K = 20) ----
  uint32_t ra[3][4];
  #pragma unroll
  for (int ks = 0; ks < 3; ks++){
    const int k = ks * 8 + kb;
    ra[ks][0] = su[OFF_RBF + rA0*20 + k];
    ra[ks][1] = su[OFF_RBF + (rA0+8)*20 + k];
    if (ks < 2){
      ra[ks][2] = su[OFF_RBF + rA0*20 + k + 4];
      ra[ks][3] = su[OFF_RBF + (rA0+8)*20 + k + 4];
    } else {
      ra[ks][2] = 0u; ra[ks][3] = 0u;
    }
  }

  const uint2* wwp = wt_ww + ((size_t)c*3*16 + nq*8)*32 + lane;

  #pragma unroll
  for (int nt = 0; nt < 8; nt++){
    const int cc = nb + nt*8 + 2*kb;
    const float2 bp = *(const float2*)(bphi_g + c*F + cc);
    const float2 bw = *(const float2*)(bw_g   + c*F + cc);
    float w4[4] = {0.f, 0.f, 0.f, 0.f};
    #pragma unroll
    for (int ks = 0; ks < 3; ks++){
      uint2 wb = __ldg(wwp + ((size_t)ks*16 + nt)*32);
      mma8(w4, ra[ks][0], ra[ks][1], ra[ks][2], ra[ks][3], wb.x, wb.y);
    }
    float s0 = (w4[0] + bw.x) * (acc[nt][0] + bp.x);
    float s1 = (w4[1] + bw.y) * (acc[nt][1] + bp.y);
    float s2 = (w4[2] + bw.x) * (acc[nt][2] + bp.x);
    float s3 = (w4[3] + bw.y) * (acc[nt][3] + bp.y);
    // stash to natural layout: conflict-free STS.64 (RSTR == 8 mod 32)
    *(float2*)(smf + buf + (rA0    )*RSTR + cc) = make_float2(s0, s1);
    *(float2*)(smf + buf + (rA0 + 8)*RSTR + cc) = make_float2(s2, s3);
  }
}

__global__ void __launch_bounds__(NTHREADS, 2)
fused_message_kernel(
    const float* __restrict__ s_g, const float* __restrict__ r_g,
    const float* __restrict__ v_g, const int*   __restrict__ idx_g,
    const float* __restrict__ bphi_g, const float* __restrict__ bw_g,
    float* __restrict__ out_v, float* __restrict__ out_s, int E)
{
  extern __shared__ float smf[];
  uint32_t* su = (uint32_t*)smf;
  const int tid  = threadIdx.x;
  const int wid  = tid >> 5;
  const int lane = tid & 31;
  const int eb   = blockIdx.x * TM;
  const int* idx_sm = (const int*)(smf + OFF_IDX);

  // ---- prologue ----
  if (wid == 0){
    float gs = 0.f;
    #pragma unroll
    for (int j = 0; j < 16; j++) gs += g_part[lane + 32*j];
    #pragma unroll
    for (int o = 16; o > 0; o >>= 1) gs += __shfl_xor_sync(0xffffffffu, gs, o);
    if (lane == 0) smf[OFF_G] = rsqrtf(gs);
  }
  // s tile -> tf32 [64][136] interleaved, STS.128 stores (8-k groups)
  {
    const uint4* s4 = (const uint4*)s_g;
    #pragma unroll
    for (int it = 0; it < 4; it++){
      int i = it * NTHREADS + tid;      // 1024 8-k groups
      int m = i >> 4, j = i & 15;
      uint4 A0 = make_uint4(0u,0u,0u,0u), A1 = make_uint4(0u,0u,0u,0u);
      if (eb + m < E){
        A0 = s4[(size_t)(eb + m) * 32 + 2*j];
        A1 = s4[(size_t)(eb + m) * 32 + 2*j + 1];
      }
      uint4 t0, t1;
      t0.x = to_tf32(__uint_as_float(A0.x)); t0.y = to_tf32(__uint_as_float(A1.x));
      t0.z = to_tf32(__uint_as_float(A0.y)); t0.w = to_tf32(__uint_as_float(A1.y));
      t1.x = to_tf32(__uint_as_float(A0.z)); t1.y = to_tf32(__uint_as_float(A1.z));
      t1.z = to_tf32(__uint_as_float(A0.w)); t1.w = to_tf32(__uint_as_float(A1.w));
      *(uint4*)(su + OFF_S + m*RSTR + 8*j)     = t0;
      *(uint4*)(su + OFF_S + m*RSTR + 8*j + 4) = t1;
    }
  }
  __syncthreads();   // g ready
  // rbf / rn / idx
  if (tid < TM){
    int ee = eb + tid;
    float rxv = 0.f, ryv = 0.f, rzv = 0.f;
    int node = 0;
    if (ee < E){
      rxv = r_g[3*ee+0]; ryv = r_g[3*ee+1]; rzv = r_g[3*ee+2];
      node = idx_g[ee];
    }
    ((int*)(smf + OFF_IDX))[tid] = node;
    float rn = sqrtf(fmaf(rxv,rxv, fmaf(ryv,ryv, rzv*rzv)));
    float invg = smf[OFF_G];
    smf[OFF_RN + tid*4+0] = rxv*invg;
    smf[OFF_RN + tid*4+1] = ryv*invg;
    smf[OFF_RN + tid*4+2] = rzv*invg;
    smf[OFF_RN + tid*4+3] = 0.f;
    if (ee < E){
      float inv_rn = 1.f / rn;
      const float c0 = 0.62831853071795864769f;  // pi / R_CUT
      #pragma unroll
      for (int k = 0; k < NRBF; k++){
        float t  = sinf((float)(k+1) * c0 * rn) * inv_rn;
        float rb = (t <= 5.0f) ? 0.5f*(cosf(c0*t) + 1.f) : 0.f;
        su[OFF_RBF + tid*20 + k] = to_tf32(rb);
      }
    } else {
      #pragma unroll
      for (int k = 0; k < NRBF; k++) su[OFF_RBF + tid*20 + k] = 0u;
    }
  }
  __syncthreads();

  // ===== chunk c=1 -> stash P1 =====
  run_chunk(su, smf, tid, 1, OFF_P1, bphi_g, bw_g);
  __syncthreads();

  // ===== epilogue S: row-major coalesced scatter of out_s =====
  #pragma unroll
  for (int i = 0; i < 8; i++){
    const int row = wid*8 + i;
    const int e   = eb + row;
    const int node = idx_sm[row];
    float4 val = *(const float4*)(smf + OFF_P1 + row*RSTR + lane*4);
    if (e < E) red4(out_s + (size_t)node*F + lane*4, val.x, val.y, val.z, val.w);
  }
  __syncthreads();   // P1 free for reuse

  // ===== chunks c=0 -> P1, c=2 -> P2 =====
  run_chunk(su, smf, tid, 0, OFF_P1, bphi_g, bw_g);
  run_chunk(su, smf, tid, 2, OFF_P2, bphi_g, bw_g);
  __syncthreads();

  // ===== epilogue V: row-major coalesced v_msg scatter =====
  #pragma unroll
  for (int i = 0; i < 8; i++){
    const int row = wid*8 + i;
    const int e   = eb + row;
    const int node = idx_sm[row];
    float4 sv4 = *(const float4*)(smf + OFF_P1 + row*RSTR + lane*4);
    float4 sr4 = *(const float4*)(smf + OFF_P2 + row*RSTR + lane*4);
    if (e < E){
      const float* vp = v_g   + (size_t)e    * 3*F + lane*4;
      float*       op = out_v + (size_t)node * 3*F + lane*4;
      #pragma unroll
      for (int d = 0; d < 3; d++){
        const float rd = smf[OFF_RN + row*4 + d];
        const float4 vv = *(const float4*)(vp + d*F);
        red4(op + d*F,
             fmaf(sv4.x, vv.x, sr4.x*rd), fmaf(sv4.y, vv.y, sr4.y*rd),
             fmaf(sv4.z, vv.z, sr4.z*rd), fmaf(sv4.w, vv.w, sr4.w*rd));
      }
    }
  }
}

extern "C" void kernel_launch(void* const* d_in, const int* in_sizes, int n_in,
                              void* d_out, int out_size){
  const float* s_g  = (const float*)d_in[0];
  const float* r_g  = (const float*)d_in[1];
  const float* v_g  = (const float*)d_in[2];
  const int*   idx  = (const int*)  d_in[3];
  const float* Wp   = (const float*)d_in[4];
  const float* bphi = (const float*)d_in[5];
  const float* Ww   = (const float*)d_in[6];
  const float* bw   = (const float*)d_in[7];
  const int E = in_sizes[1] / 3;            // r is (E,3)
  const int N = out_size / (4*F);           // out = out_v (N*3*F) ++ out_s (N*F)
  float* out_v = (float*)d_out;
  float* out_s = out_v + (size_t)N*3*F;

  prep_kernel<<<512, 256>>>(r_g, 3*E, (float4*)d_out, out_size/4, Wp, Ww);
  cudaFuncSetAttribute(fused_message_kernel,
                       cudaFuncAttributeMaxDynamicSharedMemorySize, SMEM_BYTES);
  const int blocks = (E + TM - 1) / TM;
  fused_message_kernel<<<blocks, NTHREADS, SMEM_BYTES>>>(
      s_g, r_g, v_g, idx, bphi, bw, out_v, out_s, E);
}